// round 16
// baseline (speedup 1.0000x reference)
#include <cuda_runtime.h>

// AdvancedLearnableEntropyPooling2D: 2x2/stride-2 entropy pooling, NHWC.
// x: [32, 256, 256, 128] f32 -> out: [32, 128, 128, 128] f32
// out[b,ho,wo,c] = entropy(softmax over 2x2 window at channel c) * w[c] + bias[c]
//
// PERSISTENT grid-stride variant of the R3 winner:
//   - exactly one wave of CTAs (148 SMs x 6 CTAs = 888 blocks, 256 thr);
//     each warp loops over pixel-pairs with stride = total warps.
//   - removes the ~37 wave transitions of the 32768-CTA launch and keeps a
//     continuous LDG stream per warp (next iteration's 8 loads issue while
//     this iteration's MUFU chain drains).
//   - per iteration: 2x 2KB contiguous input row segments (MLP=8),
//     1KB contiguous store; every access a full 512B warp segment.
// Entropy: H = log(S) - (sum e_i*d_i)/S with d_i = a_i - m (max-shifted).

static __device__ __forceinline__ float entropy4(float a0, float a1, float a2, float a3) {
    float m  = fmaxf(fmaxf(a0, a1), fmaxf(a2, a3));
    float d0 = a0 - m, d1 = a1 - m, d2 = a2 - m, d3 = a3 - m;
    float e0 = __expf(d0), e1 = __expf(d1), e2 = __expf(d2), e3 = __expf(d3);
    float S  = (e0 + e1) + (e2 + e3);
    float t  = fmaf(e0, d0, fmaf(e1, d1, fmaf(e2, d2, e3 * d3)));
    return __logf(S) - t * __fdividef(1.0f, S);
}

#define NUM_CTAS 888

__global__ void __launch_bounds__(256)
entropy_pool_kernel(const float4* __restrict__ x,
                    const float4* __restrict__ wgt,
                    const float4* __restrict__ bias,
                    float4* __restrict__ out) {
    const int W    = 256;      // input width
    const int Ho   = 128, Wo = 128;
    const int CB   = 32;       // 128 channels / 4 per float4
    const int WoP  = Wo / 2;   // pixel-pairs per output row = 64
    const int NPAIRS = 32 * 128 * 64;          // 262144 pixel-pairs total
    const int rowpitch = W * CB;               // 8192 float4 per input row

    int lane   = threadIdx.x & 31;
    int warp0  = (blockIdx.x * blockDim.x + threadIdx.x) >> 5;  // starting pair id
    const int wstride = NUM_CTAS * (256 / 32);                  // total warps = 7104

    float4 wv = wgt[lane];
    float4 bv = bias[lane];

    for (int wid = warp0; wid < NPAIRS; wid += wstride) {
        // wid -> (b, ho, wop); WoP=64 (6 bits), Ho=128 (7 bits), B=32
        int wop = wid & (WoP - 1);
        int t   = wid >> 6;
        int ho  = t & (Ho - 1);
        int b   = t >> 7;

        int base = (b * 256 + 2 * ho) * rowpitch + (4 * wop) * CB + lane;
        const float4* r0 = x + base;
        const float4* r1 = r0 + rowpitch;

        // 8 independent streaming loads, all full 512B warp segments
        float4 a00 = __ldcs(r0);
        float4 a01 = __ldcs(r0 + CB);
        float4 b00 = __ldcs(r0 + 2 * CB);
        float4 b01 = __ldcs(r0 + 3 * CB);
        float4 a10 = __ldcs(r1);
        float4 a11 = __ldcs(r1 + CB);
        float4 b10 = __ldcs(r1 + 2 * CB);
        float4 b11 = __ldcs(r1 + 3 * CB);

        float4 oA, oB;
        oA.x = fmaf(entropy4(a00.x, a01.x, a10.x, a11.x), wv.x, bv.x);
        oA.y = fmaf(entropy4(a00.y, a01.y, a10.y, a11.y), wv.y, bv.y);
        oA.z = fmaf(entropy4(a00.z, a01.z, a10.z, a11.z), wv.z, bv.z);
        oA.w = fmaf(entropy4(a00.w, a01.w, a10.w, a11.w), wv.w, bv.w);
        oB.x = fmaf(entropy4(b00.x, b01.x, b10.x, b11.x), wv.x, bv.x);
        oB.y = fmaf(entropy4(b00.y, b01.y, b10.y, b11.y), wv.y, bv.y);
        oB.z = fmaf(entropy4(b00.z, b01.z, b10.z, b11.z), wv.z, bv.z);
        oB.w = fmaf(entropy4(b00.w, b01.w, b10.w, b11.w), wv.w, bv.w);

        // output pixels (wo=2*wop, 2*wop+1): contiguous 1KB per warp
        float4* op = out + ((b * Ho + ho) * Wo + 2 * wop) * CB + lane;
        __stcs(op,      oA);
        __stcs(op + CB, oB);
    }
}

extern "C" void kernel_launch(void* const* d_in, const int* in_sizes, int n_in,
                              void* d_out, int out_size) {
    const float4* x    = (const float4*)d_in[0];
    const float4* wgt  = (const float4*)d_in[1];
    const float4* bias = (const float4*)d_in[2];
    float4* out        = (float4*)d_out;

    // One persistent wave: 148 SMs x 6 CTAs = 888 blocks x 256 threads.
    entropy_pool_kernel<<<NUM_CTAS, 256>>>(x, wgt, bias, out);
}